// round 11
// baseline (speedup 1.0000x reference)
#include <cuda_runtime.h>

#define NUM_USERS 30000
#define NN 60000            // total nodes
#define EE 800000           // edges
#define KK 64               // embed dim (4 intents x 16)
#define NB 235              // ceil(NN/256) scan blocks

// -------- device scratch --------
__device__ float  d_TT32[(size_t)NN * KK];   // tanh(per-intent l2norm(ego))
__device__ float  d_EGO32[(size_t)NN * KK];  // ego[n]/sqrt(deg[n])
__device__ float  d_SC[(size_t)EE * 4];      // softmax scores at SORTED edge pos
__device__ int    d_deg[NN];
__device__ float  d_ratio[NN * 4];           // sqrt(deg[n]) * rsqrt(deg2[n,intent])
__device__ int    d_rowptr[NN + 1];
__device__ int    d_cursor[NN];
__device__ int    d_sorted_t[EE];            // tails grouped by head
__device__ int    d_partial[256];            // scan block sums
__device__ unsigned d_bar = 0;               // monotonic grid-barrier counter

// -------- packed f32x2 helpers (sm_103a FADD2/FFMA2; PTX-only) --------
typedef unsigned long long u64;
union F2U { float2 f; u64 u; };

__device__ __forceinline__ u64 f2_add(u64 a, u64 b) {
    u64 r; asm("add.rn.f32x2 %0, %1, %2;" : "=l"(r) : "l"(a), "l"(b)); return r;
}
__device__ __forceinline__ u64 f2_fma(u64 a, u64 b, u64 c) {
    u64 r; asm("fma.rn.f32x2 %0, %1, %2, %3;" : "=l"(r) : "l"(a), "l"(b), "l"(c)); return r;
}
__device__ __forceinline__ u64 f2_pack(float lo, float hi) {
    F2U t; t.f = make_float2(lo, hi); return t.u;
}
__device__ __forceinline__ float2 f2_unpack(u64 a) { F2U t; t.u = a; return t.f; }

__device__ __forceinline__ const float4* ego_row(const float* Gu, const float* Gi, int t) {
    const float* p = (t < NUM_USERS) ? (Gu + (size_t)t * KK)
                                     : (Gi + (size_t)(t - NUM_USERS) * KK);
    return reinterpret_cast<const float4*>(p);
}

__device__ __forceinline__ float fast_tanh(float x) {   // |x|<=1 here
    float e = __expf(2.f * x);
    return __fdividef(e - 1.f, e + 1.f);
}

// single-wave monotonic grid barrier (replay-safe; all blocks co-resident)
__device__ __forceinline__ void gridbar() {
    __syncthreads();
    if (threadIdx.x == 0) {
        __threadfence();
        atomicAdd(&d_bar, 1u);
        unsigned token;
        asm volatile("ld.acquire.gpu.global.u32 %0, [%1];" : "=r"(token) : "l"(&d_bar) : "memory");
        unsigned target = ((token - 1u) / gridDim.x + 1u) * gridDim.x;
        unsigned v = token;
        while (v < target) {
            __nanosleep(32);
            asm volatile("ld.acquire.gpu.global.u32 %0, [%1];" : "=r"(v) : "l"(&d_bar) : "memory");
        }
    }
    __syncthreads();
}

// block-wide exclusive scan of one int per thread (blockDim=256)
__device__ __forceinline__ int block_exscan(int v, int* sm) {
    int lane = threadIdx.x & 31, w = threadIdx.x >> 5;
    int x = v;
#pragma unroll
    for (int d = 1; d < 32; d <<= 1) {
        int y = __shfl_up_sync(0xffffffffu, x, d);
        if (lane >= d) x += y;
    }
    if (lane == 31) sm[w] = x;
    __syncthreads();
    if (w == 0) {
        int s = (lane < 8) ? sm[lane] : 0;
#pragma unroll
        for (int d = 1; d < 8; d <<= 1) {
            int y = __shfl_up_sync(0xffffffffu, s, d);
            if (lane >= d) s += y;
        }
        if (lane < 8) sm[lane] = s;
    }
    __syncthreads();
    int off = (w > 0) ? sm[w - 1] : 0;
    return off + x - v;
}

// -------- kernels --------

#define DEG_BLKS  ((EE / 8 + 255) / 256)
#define SCAT_BLKS ((EE / 8 + 255) / 256)
#define NODE_BLKS ((NN * 16 + 255) / 256)

// fused: blocks [0, DEG_BLKS) count head degrees (8 edges/thread); rest TT32
__global__ void k_deg_tt(const int* __restrict__ eh,
                         const float* __restrict__ Gu, const float* __restrict__ Gi) {
    if (blockIdx.x < DEG_BLKS) {
        int g = blockIdx.x * blockDim.x + threadIdx.x;
        if (g >= EE / 8) return;
        int4 a = __ldg(&reinterpret_cast<const int4*>(eh)[2 * g]);
        int4 b = __ldg(&reinterpret_cast<const int4*>(eh)[2 * g + 1]);
        atomicAdd(&d_deg[a.x], 1); atomicAdd(&d_deg[a.y], 1);
        atomicAdd(&d_deg[a.z], 1); atomicAdd(&d_deg[a.w], 1);
        atomicAdd(&d_deg[b.x], 1); atomicAdd(&d_deg[b.y], 1);
        atomicAdd(&d_deg[b.z], 1); atomicAdd(&d_deg[b.w], 1);
    } else {
        int tid = (blockIdx.x - DEG_BLKS) * blockDim.x + threadIdx.x;
        if (tid >= NN * 16) return;
        int n = tid >> 4;
        float4 v = __ldg(&ego_row(Gu, Gi, n)[tid & 15]);
        float ss = v.x * v.x + v.y * v.y + v.z * v.z + v.w * v.w;
        ss += __shfl_xor_sync(0xffffffffu, ss, 1);
        ss += __shfl_xor_sync(0xffffffffu, ss, 2);
        float it = rsqrtf(fmaxf(ss, 1e-12f));
        reinterpret_cast<float4*>(d_TT32)[tid] =
            make_float4(fast_tanh(v.x * it), fast_tanh(v.y * it),
                        fast_tanh(v.z * it), fast_tanh(v.w * it));
    }
}

// fused two-stage scan in one kernel (NB blocks = single wave; gridbar safe)
__global__ void k_scan2() {
    __shared__ int sm[8];
    __shared__ int base_sh;
    int i = blockIdx.x * 256 + threadIdx.x;
    int v = (i < NN) ? d_deg[i] : 0;
    int ex = block_exscan(v, sm);
    if (threadIdx.x == 255) d_partial[blockIdx.x] = ex + v;
    gridbar();
    if (threadIdx.x < 32) {
        int s = 0;
        for (int t = threadIdx.x; t < blockIdx.x; t += 32) s += d_partial[t];
#pragma unroll
        for (int d = 16; d >= 1; d >>= 1) s += __shfl_xor_sync(0xffffffffu, s, d);
        if (threadIdx.x == 0) base_sh = s;
    }
    __syncthreads();
    ex += base_sh;
    if (i < NN) { d_rowptr[i] = ex; d_cursor[i] = ex; }
    if (i == NN - 1) d_rowptr[NN] = EE;
}

// fused: blocks [0, SCAT_BLKS) scatter tails (8 edges/thread); rest EGO32
__global__ void k_scatter_ego(const int* __restrict__ eh, const int* __restrict__ et,
                              const float* __restrict__ Gu, const float* __restrict__ Gi) {
    if (blockIdx.x < SCAT_BLKS) {
        int g = blockIdx.x * blockDim.x + threadIdx.x;
        if (g >= EE / 8) return;
        int4 ha = __ldg(&reinterpret_cast<const int4*>(eh)[2 * g]);
        int4 hb = __ldg(&reinterpret_cast<const int4*>(eh)[2 * g + 1]);
        int4 ta = __ldg(&reinterpret_cast<const int4*>(et)[2 * g]);
        int4 tb = __ldg(&reinterpret_cast<const int4*>(et)[2 * g + 1]);
        d_sorted_t[atomicAdd(&d_cursor[ha.x], 1)] = ta.x;
        d_sorted_t[atomicAdd(&d_cursor[ha.y], 1)] = ta.y;
        d_sorted_t[atomicAdd(&d_cursor[ha.z], 1)] = ta.z;
        d_sorted_t[atomicAdd(&d_cursor[ha.w], 1)] = ta.w;
        d_sorted_t[atomicAdd(&d_cursor[hb.x], 1)] = tb.x;
        d_sorted_t[atomicAdd(&d_cursor[hb.y], 1)] = tb.y;
        d_sorted_t[atomicAdd(&d_cursor[hb.z], 1)] = tb.z;
        d_sorted_t[atomicAdd(&d_cursor[hb.w], 1)] = tb.w;
    } else {
        int tid = (blockIdx.x - SCAT_BLKS) * blockDim.x + threadIdx.x;
        if (tid >= NN * 16) return;
        int n = tid >> 4;
        float4 v = __ldg(&ego_row(Gu, Gi, n)[tid & 15]);
        float w = rsqrtf((float)d_deg[n]);   // rs1 folded into EGO32
        reinterpret_cast<float4*>(d_EGO32)[tid] =
            make_float4(w * v.x, w * v.y, w * v.z, w * v.w);
    }
}

// Warp-per-row: SpMM1 (f32x2 adds) -> l2norm -> transpose -> attention in
// (slot,intent) layout (f32x2 FMA dot) -> ratio.
__global__ void k_row1attn() {
    int wid = (blockIdx.x * blockDim.x + threadIdx.x) >> 5;
    if (wid >= NN) return;
    int lane = threadIdx.x & 31, half = lane >> 4, c = lane & 15;
    int start = d_rowptr[wid], end = d_rowptr[wid + 1];
    const ulonglong2* EG = reinterpret_cast<const ulonglong2*>(d_EGO32);

    // ---- pass 1: Z1 accumulate with packed FADD2 (halves layout, unroll-2) ----
    u64 accA = 0ull, accB = 0ull;                 // packed (x,y) and (z,w)
    int j = start + half;
    for (; j + 2 < end; j += 4) {
        int t0 = __ldg(&d_sorted_t[j]);
        int t1 = __ldg(&d_sorted_t[j + 2]);
        ulonglong2 e0 = __ldg(&EG[(size_t)t0 * 16 + c]);
        ulonglong2 e1 = __ldg(&EG[(size_t)t1 * 16 + c]);
        accA = f2_add(accA, e0.x); accB = f2_add(accB, e0.y);
        accA = f2_add(accA, e1.x); accB = f2_add(accB, e1.y);
    }
    if (j < end) {
        int t = __ldg(&d_sorted_t[j]);
        ulonglong2 e = __ldg(&EG[(size_t)t * 16 + c]);
        accA = f2_add(accA, e.x); accB = f2_add(accB, e.y);
    }
    float2 aA = f2_unpack(accA), aB = f2_unpack(accB);
    float4 acc = make_float4(aA.x, aA.y, aB.x, aB.y);
    acc.x += __shfl_xor_sync(0xffffffffu, acc.x, 16);
    acc.y += __shfl_xor_sync(0xffffffffu, acc.y, 16);
    acc.z += __shfl_xor_sync(0xffffffffu, acc.z, 16);
    acc.w += __shfl_xor_sync(0xffffffffu, acc.w, 16);
    float ss = acc.x * acc.x + acc.y * acc.y + acc.z * acc.z + acc.w * acc.w;
    ss += __shfl_xor_sync(0xffffffffu, ss, 1);
    ss += __shfl_xor_sync(0xffffffffu, ss, 2);
    float ih = rsqrtf(fmaxf(ss, 1e-12f));
    float4 hvf = make_float4(acc.x * ih, acc.y * ih, acc.z * ih, acc.w * ih);

    // ---- transpose hv into (slot,intent) layout: lane = 4*slot + intent ----
    int slot = lane >> 2, it = lane & 3;
    float hv[16];
#pragma unroll
    for (int k = 0; k < 16; k++) {
        int src = it * 4 + (k >> 2);
        float v;
        switch (k & 3) {
            case 0: v = __shfl_sync(0xffffffffu, hvf.x, src); break;
            case 1: v = __shfl_sync(0xffffffffu, hvf.y, src); break;
            case 2: v = __shfl_sync(0xffffffffu, hvf.z, src); break;
            default: v = __shfl_sync(0xffffffffu, hvf.w, src); break;
        }
        hv[k] = v;
    }
    u64 hv2[8];
#pragma unroll
    for (int k = 0; k < 8; k++) hv2[k] = f2_pack(hv[2 * k], hv[2 * k + 1]);

    // ---- pass 2: 8 edges/iter; lane=(slot,intent); packed FFMA2 dot ----
    const ulonglong2* TT = reinterpret_cast<const ulonglong2*>(d_TT32);
    float dsum = 0.f;
    for (int base = start; base < end; base += 8) {
        int j2 = base + slot;
        bool act = (j2 < end);
        int t = act ? __ldg(&d_sorted_t[j2]) : 0;
        size_t off = (size_t)t * 16 + it * 4;      // 16 ulonglong2 per row; 4 per intent
        ulonglong2 q0 = __ldg(&TT[off]);
        ulonglong2 q1 = __ldg(&TT[off + 1]);
        ulonglong2 q2 = __ldg(&TT[off + 2]);
        ulonglong2 q3 = __ldg(&TT[off + 3]);
        u64 acc2 = f2_fma(q0.x, hv2[0], 0ull);
        acc2 = f2_fma(q0.y, hv2[1], acc2);
        acc2 = f2_fma(q1.x, hv2[2], acc2);
        acc2 = f2_fma(q1.y, hv2[3], acc2);
        acc2 = f2_fma(q2.x, hv2[4], acc2);
        acc2 = f2_fma(q2.y, hv2[5], acc2);
        acc2 = f2_fma(q3.x, hv2[6], acc2);
        acc2 = f2_fma(q3.y, hv2[7], acc2);
        float2 pr = f2_unpack(acc2);
        float p = pr.x + pr.y;
        float ex = __expf(p);                       // "1+" & max-shift cancel
        float sum = ex + __shfl_xor_sync(0xffffffffu, ex, 1);
        sum += __shfl_xor_sync(0xffffffffu, sum, 2);
        float sc = __fdividef(ex, sum);
        if (act) {
            d_SC[(size_t)j2 * 4 + it] = sc;         // coalesced
            dsum += sc;
        }
    }
    dsum += __shfl_xor_sync(0xffffffffu, dsum, 4);
    dsum += __shfl_xor_sync(0xffffffffu, dsum, 8);
    dsum += __shfl_xor_sync(0xffffffffu, dsum, 16);
    if (lane < 4)
        d_ratio[wid * 4 + it] = sqrtf((float)(end - start)) * rsqrtf(dsum);
}

// warp-per-row SpMM2 (packed FFMA2) + final mean -> out.
//   w = SC[j]*ratio[t]; EGO32[t]=ego[t]/sqrt(deg[t])  ==  SC[j]*rsqrt(deg2[t])*ego[t]
__global__ void k_row2(const float* __restrict__ Gu, const float* __restrict__ Gi,
                       float* __restrict__ out) {
    int wid = (blockIdx.x * blockDim.x + threadIdx.x) >> 5;
    if (wid >= NN) return;
    int lane = threadIdx.x & 31, half = lane >> 4, c = lane & 15;
    int intent = c >> 2;
    int start = d_rowptr[wid], end = d_rowptr[wid + 1];
    const ulonglong2* EG = reinterpret_cast<const ulonglong2*>(d_EGO32);

    u64 accA = 0ull, accB = 0ull;
    int j = start + half;
    for (; j + 2 < end; j += 4) {
        int t0 = __ldg(&d_sorted_t[j]);
        int t1 = __ldg(&d_sorted_t[j + 2]);
        float w0 = __ldg(&d_SC[(size_t)j * 4 + intent]) * __ldg(&d_ratio[t0 * 4 + intent]);
        float w1 = __ldg(&d_SC[(size_t)(j + 2) * 4 + intent]) * __ldg(&d_ratio[t1 * 4 + intent]);
        ulonglong2 e0 = __ldg(&EG[(size_t)t0 * 16 + c]);
        ulonglong2 e1 = __ldg(&EG[(size_t)t1 * 16 + c]);
        u64 wp0 = f2_pack(w0, w0), wp1 = f2_pack(w1, w1);
        accA = f2_fma(wp0, e0.x, accA); accB = f2_fma(wp0, e0.y, accB);
        accA = f2_fma(wp1, e1.x, accA); accB = f2_fma(wp1, e1.y, accB);
    }
    if (j < end) {
        int t = __ldg(&d_sorted_t[j]);
        float w = __ldg(&d_SC[(size_t)j * 4 + intent]) * __ldg(&d_ratio[t * 4 + intent]);
        ulonglong2 e = __ldg(&EG[(size_t)t * 16 + c]);
        u64 wp = f2_pack(w, w);
        accA = f2_fma(wp, e.x, accA); accB = f2_fma(wp, e.y, accB);
    }
    float2 aA = f2_unpack(accA), aB = f2_unpack(accB);
    float4 acc = make_float4(aA.x, aA.y, aB.x, aB.y);
    acc.x += __shfl_xor_sync(0xffffffffu, acc.x, 16);
    acc.y += __shfl_xor_sync(0xffffffffu, acc.y, 16);
    acc.z += __shfl_xor_sync(0xffffffffu, acc.z, 16);
    acc.w += __shfl_xor_sync(0xffffffffu, acc.w, 16);
    if (half == 0) {
        float r2 = d_ratio[wid * 4 + intent] * rsqrtf((float)(end - start));
        float4 a = __ldg(&ego_row(Gu, Gi, wid)[c]);
        reinterpret_cast<float4*>(out)[(size_t)wid * 16 + c] =
            make_float4(0.5f * (a.x + r2 * acc.x), 0.5f * (a.y + r2 * acc.y),
                        0.5f * (a.z + r2 * acc.z), 0.5f * (a.w + r2 * acc.w));
    }
}

extern "C" void kernel_launch(void* const* d_in, const int* in_sizes, int n_in,
                              void* d_out, int out_size) {
    const float* Gu = (const float*)d_in[0];
    const float* Gi = (const float*)d_in[1];
    const int*   eh = (const int*)d_in[2];
    const int*   et = (const int*)d_in[3];
    float* out = (float*)d_out;

    void* degp = nullptr;
    cudaGetSymbolAddress(&degp, d_deg);
    cudaMemsetAsync(degp, 0, NN * sizeof(int));

    const int T = 256;
    const int ROWG = (NN * 32 + T - 1) / T;   // warp-per-row grids
    k_deg_tt     <<<DEG_BLKS + NODE_BLKS, T>>>(eh, Gu, Gi);
    k_scan2      <<<NB, 256>>>();
    k_scatter_ego<<<SCAT_BLKS + NODE_BLKS, T>>>(eh, et, Gu, Gi);
    k_row1attn   <<<ROWG, T>>>();
    k_row2       <<<ROWG, T>>>(Gu, Gi, out);
}

// round 12
// speedup vs baseline: 1.2232x; 1.2232x over previous
#include <cuda_runtime.h>
#include <cuda_fp16.h>

#define NUM_USERS 30000
#define NN 60000            // total nodes
#define EE 800000           // edges
#define KK 64               // embed dim (4 intents x 16)
#define NB 235              // ceil(NN/256) scan blocks

// -------- device scratch --------
__device__ __half d_TT16[(size_t)NN * KK];   // fp16 tanh(per-intent l2norm(ego))
__device__ __half d_EGO16[(size_t)NN * KK];  // fp16 ego[n]/sqrt(deg[n])
__device__ float  d_SC[(size_t)EE * 4];      // softmax scores at SORTED edge pos
__device__ int    d_deg[NN];
__device__ float  d_ratio[NN * 4];           // sqrt(deg[n]) * rsqrt(deg2[n,intent])
__device__ int    d_rowptr[NN + 1];
__device__ int    d_cursor[NN];
__device__ int    d_sorted_t[EE];            // tails grouped by head
__device__ int    d_partial[256];            // scan block sums
__device__ unsigned d_bar = 0;               // monotonic grid-barrier counter

__device__ __forceinline__ const float4* ego_row(const float* Gu, const float* Gi, int t) {
    const float* p = (t < NUM_USERS) ? (Gu + (size_t)t * KK)
                                     : (Gi + (size_t)(t - NUM_USERS) * KK);
    return reinterpret_cast<const float4*>(p);
}

__device__ __forceinline__ float4 h4_to_f4(uint2 p) {
    float2 a = __half22float2(*reinterpret_cast<const __half2*>(&p.x));
    float2 b = __half22float2(*reinterpret_cast<const __half2*>(&p.y));
    return make_float4(a.x, a.y, b.x, b.y);
}

__device__ __forceinline__ float fast_tanh(float x) {   // |x|<=1 here
    float e = __expf(2.f * x);
    return __fdividef(e - 1.f, e + 1.f);
}

// single-wave monotonic grid barrier (replay-safe; all blocks co-resident)
__device__ __forceinline__ void gridbar() {
    __syncthreads();
    if (threadIdx.x == 0) {
        __threadfence();
        atomicAdd(&d_bar, 1u);
        unsigned token;
        asm volatile("ld.acquire.gpu.global.u32 %0, [%1];" : "=r"(token) : "l"(&d_bar) : "memory");
        unsigned target = ((token - 1u) / gridDim.x + 1u) * gridDim.x;
        unsigned v = token;
        while (v < target) {
            __nanosleep(32);
            asm volatile("ld.acquire.gpu.global.u32 %0, [%1];" : "=r"(v) : "l"(&d_bar) : "memory");
        }
    }
    __syncthreads();
}

// block-wide exclusive scan of one int per thread (blockDim=256)
__device__ __forceinline__ int block_exscan(int v, int* sm) {
    int lane = threadIdx.x & 31, w = threadIdx.x >> 5;
    int x = v;
#pragma unroll
    for (int d = 1; d < 32; d <<= 1) {
        int y = __shfl_up_sync(0xffffffffu, x, d);
        if (lane >= d) x += y;
    }
    if (lane == 31) sm[w] = x;
    __syncthreads();
    if (w == 0) {
        int s = (lane < 8) ? sm[lane] : 0;
#pragma unroll
        for (int d = 1; d < 8; d <<= 1) {
            int y = __shfl_up_sync(0xffffffffu, s, d);
            if (lane >= d) s += y;
        }
        if (lane < 8) sm[lane] = s;
    }
    __syncthreads();
    int off = (w > 0) ? sm[w - 1] : 0;
    return off + x - v;
}

// -------- kernels --------

#define DEG_BLKS  ((EE / 8 + 255) / 256)
#define SCAT_BLKS ((EE / 8 + 255) / 256)
#define NODE_BLKS ((NN * 16 + 255) / 256)

// fused: blocks [0, DEG_BLKS) count head degrees (8 edges/thread); rest TT16
__global__ void k_deg_tt(const int* __restrict__ eh,
                         const float* __restrict__ Gu, const float* __restrict__ Gi) {
    if (blockIdx.x < DEG_BLKS) {
        int g = blockIdx.x * blockDim.x + threadIdx.x;
        if (g >= EE / 8) return;
        int4 a = __ldg(&reinterpret_cast<const int4*>(eh)[2 * g]);
        int4 b = __ldg(&reinterpret_cast<const int4*>(eh)[2 * g + 1]);
        atomicAdd(&d_deg[a.x], 1); atomicAdd(&d_deg[a.y], 1);
        atomicAdd(&d_deg[a.z], 1); atomicAdd(&d_deg[a.w], 1);
        atomicAdd(&d_deg[b.x], 1); atomicAdd(&d_deg[b.y], 1);
        atomicAdd(&d_deg[b.z], 1); atomicAdd(&d_deg[b.w], 1);
    } else {
        int tid = (blockIdx.x - DEG_BLKS) * blockDim.x + threadIdx.x;
        if (tid >= NN * 16) return;
        int n = tid >> 4;
        float4 v = __ldg(&ego_row(Gu, Gi, n)[tid & 15]);
        float ss = v.x * v.x + v.y * v.y + v.z * v.z + v.w * v.w;
        ss += __shfl_xor_sync(0xffffffffu, ss, 1);
        ss += __shfl_xor_sync(0xffffffffu, ss, 2);
        float it = rsqrtf(fmaxf(ss, 1e-12f));
        __half2 t0 = __floats2half2_rn(fast_tanh(v.x * it), fast_tanh(v.y * it));
        __half2 t1 = __floats2half2_rn(fast_tanh(v.z * it), fast_tanh(v.w * it));
        uint2 tp; tp.x = *reinterpret_cast<unsigned*>(&t0);
                  tp.y = *reinterpret_cast<unsigned*>(&t1);
        reinterpret_cast<uint2*>(d_TT16)[tid] = tp;
    }
}

// fused two-stage scan in one kernel (NB blocks = single wave; gridbar safe)
__global__ void k_scan2() {
    __shared__ int sm[8];
    __shared__ int base_sh;
    int i = blockIdx.x * 256 + threadIdx.x;
    int v = (i < NN) ? d_deg[i] : 0;
    int ex = block_exscan(v, sm);
    if (threadIdx.x == 255) d_partial[blockIdx.x] = ex + v;
    gridbar();
    if (threadIdx.x < 32) {
        int s = 0;
        for (int t = threadIdx.x; t < blockIdx.x; t += 32) s += d_partial[t];
#pragma unroll
        for (int d = 16; d >= 1; d >>= 1) s += __shfl_xor_sync(0xffffffffu, s, d);
        if (threadIdx.x == 0) base_sh = s;
    }
    __syncthreads();
    ex += base_sh;
    if (i < NN) { d_rowptr[i] = ex; d_cursor[i] = ex; }
    if (i == NN - 1) d_rowptr[NN] = EE;
}

// fused: blocks [0, SCAT_BLKS) scatter tails (8 edges/thread); rest EGO16
__global__ void k_scatter_ego(const int* __restrict__ eh, const int* __restrict__ et,
                              const float* __restrict__ Gu, const float* __restrict__ Gi) {
    if (blockIdx.x < SCAT_BLKS) {
        int g = blockIdx.x * blockDim.x + threadIdx.x;
        if (g >= EE / 8) return;
        int4 ha = __ldg(&reinterpret_cast<const int4*>(eh)[2 * g]);
        int4 hb = __ldg(&reinterpret_cast<const int4*>(eh)[2 * g + 1]);
        int4 ta = __ldg(&reinterpret_cast<const int4*>(et)[2 * g]);
        int4 tb = __ldg(&reinterpret_cast<const int4*>(et)[2 * g + 1]);
        d_sorted_t[atomicAdd(&d_cursor[ha.x], 1)] = ta.x;
        d_sorted_t[atomicAdd(&d_cursor[ha.y], 1)] = ta.y;
        d_sorted_t[atomicAdd(&d_cursor[ha.z], 1)] = ta.z;
        d_sorted_t[atomicAdd(&d_cursor[ha.w], 1)] = ta.w;
        d_sorted_t[atomicAdd(&d_cursor[hb.x], 1)] = tb.x;
        d_sorted_t[atomicAdd(&d_cursor[hb.y], 1)] = tb.y;
        d_sorted_t[atomicAdd(&d_cursor[hb.z], 1)] = tb.z;
        d_sorted_t[atomicAdd(&d_cursor[hb.w], 1)] = tb.w;
    } else {
        int tid = (blockIdx.x - SCAT_BLKS) * blockDim.x + threadIdx.x;
        if (tid >= NN * 16) return;
        int n = tid >> 4;
        float4 v = __ldg(&ego_row(Gu, Gi, n)[tid & 15]);
        float w = rsqrtf((float)d_deg[n]);   // rs1 folded into EGO16
        __half2 e0 = __floats2half2_rn(w * v.x, w * v.y);
        __half2 e1 = __floats2half2_rn(w * v.z, w * v.w);
        uint2 ep; ep.x = *reinterpret_cast<unsigned*>(&e0);
                  ep.y = *reinterpret_cast<unsigned*>(&e1);
        reinterpret_cast<uint2*>(d_EGO16)[tid] = ep;
    }
}

// Warp-per-row: SpMM1 (halves, fp16) -> per-intent l2norm -> SMEM warp
// transpose -> attention in (slot,intent) layout -> ratio.
__global__ void __launch_bounds__(256, 6) k_row1attn() {
    __shared__ float hv_s[8][64];               // per-warp transpose buffer
    int wid = (blockIdx.x * blockDim.x + threadIdx.x) >> 5;
    if (wid >= NN) return;
    int lane = threadIdx.x & 31, half = lane >> 4, c = lane & 15;
    int wrp = (threadIdx.x >> 5);
    int start = d_rowptr[wid], end = d_rowptr[wid + 1];
    const uint2* EG = reinterpret_cast<const uint2*>(d_EGO16);

    // ---- pass 1: Z1 row accumulate (R9 body) ----
    float4 acc = make_float4(0, 0, 0, 0);
    int j = start + half;
    for (; j + 2 < end; j += 4) {
        int t0 = __ldg(&d_sorted_t[j]);
        int t1 = __ldg(&d_sorted_t[j + 2]);
        float4 s0 = h4_to_f4(__ldg(&EG[(size_t)t0 * 16 + c]));
        float4 s1 = h4_to_f4(__ldg(&EG[(size_t)t1 * 16 + c]));
        acc.x += s0.x + s1.x; acc.y += s0.y + s1.y;
        acc.z += s0.z + s1.z; acc.w += s0.w + s1.w;
    }
    if (j < end) {
        int t = __ldg(&d_sorted_t[j]);
        float4 s = h4_to_f4(__ldg(&EG[(size_t)t * 16 + c]));
        acc.x += s.x; acc.y += s.y; acc.z += s.z; acc.w += s.w;
    }
    acc.x += __shfl_xor_sync(0xffffffffu, acc.x, 16);
    acc.y += __shfl_xor_sync(0xffffffffu, acc.y, 16);
    acc.z += __shfl_xor_sync(0xffffffffu, acc.z, 16);
    acc.w += __shfl_xor_sync(0xffffffffu, acc.w, 16);
    float ss = acc.x * acc.x + acc.y * acc.y + acc.z * acc.z + acc.w * acc.w;
    ss += __shfl_xor_sync(0xffffffffu, ss, 1);
    ss += __shfl_xor_sync(0xffffffffu, ss, 2);
    float ih = rsqrtf(fmaxf(ss, 1e-12f));

    // ---- SMEM warp transpose: half 0 stores chunk-layout hv; all lanes
    //      reload their intent's 16 channels (broadcast LDS, conflict-free) ----
    if (half == 0)
        *reinterpret_cast<float4*>(&hv_s[wrp][c * 4]) =
            make_float4(acc.x * ih, acc.y * ih, acc.z * ih, acc.w * ih);
    __syncwarp();
    int slot = lane >> 2, it = lane & 3;
    float4 hA = *reinterpret_cast<const float4*>(&hv_s[wrp][it * 16]);
    float4 hB = *reinterpret_cast<const float4*>(&hv_s[wrp][it * 16 + 4]);
    float4 hC = *reinterpret_cast<const float4*>(&hv_s[wrp][it * 16 + 8]);
    float4 hD = *reinterpret_cast<const float4*>(&hv_s[wrp][it * 16 + 12]);

    // ---- pass 2: 8 edges/iter; lane=(slot,intent) (R9 body) ----
    float dsum = 0.f;
    for (int base = start; base < end; base += 8) {
        int j2 = base + slot;
        bool act = (j2 < end);
        int t = act ? __ldg(&d_sorted_t[j2]) : 0;
        const uint4* bp = reinterpret_cast<const uint4*>(d_TT16 + ((size_t)t << 6)) + (it << 1);
        uint4 q0 = __ldg(bp);
        uint4 q1 = __ldg(bp + 1);
        float2 f0 = __half22float2(*reinterpret_cast<const __half2*>(&q0.x));
        float2 f1 = __half22float2(*reinterpret_cast<const __half2*>(&q0.y));
        float2 f2 = __half22float2(*reinterpret_cast<const __half2*>(&q0.z));
        float2 f3 = __half22float2(*reinterpret_cast<const __half2*>(&q0.w));
        float2 f4 = __half22float2(*reinterpret_cast<const __half2*>(&q1.x));
        float2 f5 = __half22float2(*reinterpret_cast<const __half2*>(&q1.y));
        float2 f6 = __half22float2(*reinterpret_cast<const __half2*>(&q1.z));
        float2 f7 = __half22float2(*reinterpret_cast<const __half2*>(&q1.w));
        float p = f0.x * hA.x + f0.y * hA.y + f1.x * hA.z + f1.y * hA.w
                + f2.x * hB.x + f2.y * hB.y + f3.x * hB.z + f3.y * hB.w
                + f4.x * hC.x + f4.y * hC.y + f5.x * hC.z + f5.y * hC.w
                + f6.x * hD.x + f6.y * hD.y + f7.x * hD.z + f7.y * hD.w;
        float ex = __expf(p);                       // "1+" & max-shift cancel
        float sum = ex + __shfl_xor_sync(0xffffffffu, ex, 1);
        sum += __shfl_xor_sync(0xffffffffu, sum, 2);
        float sc = __fdividef(ex, sum);
        if (act) {
            d_SC[(size_t)j2 * 4 + it] = sc;         // coalesced
            dsum += sc;
        }
    }
    dsum += __shfl_xor_sync(0xffffffffu, dsum, 4);
    dsum += __shfl_xor_sync(0xffffffffu, dsum, 8);
    dsum += __shfl_xor_sync(0xffffffffu, dsum, 16);
    if (lane < 4)
        d_ratio[wid * 4 + it] = sqrtf((float)(end - start)) * rsqrtf(dsum);
}

// warp-per-row SpMM2 (fp16 ego, R9 body) + final mean -> out.
//   w = SC[j]*ratio[t]; EGO16[t]=ego[t]/sqrt(deg[t])  ==  SC[j]*rsqrt(deg2[t])*ego[t]
__global__ void __launch_bounds__(256, 6)
k_row2(const float* __restrict__ Gu, const float* __restrict__ Gi,
       float* __restrict__ out) {
    int wid = (blockIdx.x * blockDim.x + threadIdx.x) >> 5;
    if (wid >= NN) return;
    int lane = threadIdx.x & 31, half = lane >> 4, c = lane & 15;
    int intent = c >> 2;
    int start = d_rowptr[wid], end = d_rowptr[wid + 1];
    const uint2* EG = reinterpret_cast<const uint2*>(d_EGO16);
    float4 acc = make_float4(0, 0, 0, 0);
    int j = start + half;
    for (; j + 2 < end; j += 4) {
        int t0 = __ldg(&d_sorted_t[j]);
        int t1 = __ldg(&d_sorted_t[j + 2]);
        float w0 = __ldg(&d_SC[(size_t)j * 4 + intent]) * __ldg(&d_ratio[t0 * 4 + intent]);
        float w1 = __ldg(&d_SC[(size_t)(j + 2) * 4 + intent]) * __ldg(&d_ratio[t1 * 4 + intent]);
        float4 s0 = h4_to_f4(__ldg(&EG[(size_t)t0 * 16 + c]));
        float4 s1 = h4_to_f4(__ldg(&EG[(size_t)t1 * 16 + c]));
        acc.x += w0 * s0.x + w1 * s1.x;
        acc.y += w0 * s0.y + w1 * s1.y;
        acc.z += w0 * s0.z + w1 * s1.z;
        acc.w += w0 * s0.w + w1 * s1.w;
    }
    if (j < end) {
        int t = __ldg(&d_sorted_t[j]);
        float w = __ldg(&d_SC[(size_t)j * 4 + intent]) * __ldg(&d_ratio[t * 4 + intent]);
        float4 s = h4_to_f4(__ldg(&EG[(size_t)t * 16 + c]));
        acc.x += w * s.x; acc.y += w * s.y; acc.z += w * s.z; acc.w += w * s.w;
    }
    acc.x += __shfl_xor_sync(0xffffffffu, acc.x, 16);
    acc.y += __shfl_xor_sync(0xffffffffu, acc.y, 16);
    acc.z += __shfl_xor_sync(0xffffffffu, acc.z, 16);
    acc.w += __shfl_xor_sync(0xffffffffu, acc.w, 16);
    if (half == 0) {
        float r2 = d_ratio[wid * 4 + intent] * rsqrtf((float)(end - start));
        float4 a = __ldg(&ego_row(Gu, Gi, wid)[c]);   // self term fp32
        reinterpret_cast<float4*>(out)[(size_t)wid * 16 + c] =
            make_float4(0.5f * (a.x + r2 * acc.x), 0.5f * (a.y + r2 * acc.y),
                        0.5f * (a.z + r2 * acc.z), 0.5f * (a.w + r2 * acc.w));
    }
}

extern "C" void kernel_launch(void* const* d_in, const int* in_sizes, int n_in,
                              void* d_out, int out_size) {
    const float* Gu = (const float*)d_in[0];
    const float* Gi = (const float*)d_in[1];
    const int*   eh = (const int*)d_in[2];
    const int*   et = (const int*)d_in[3];
    float* out = (float*)d_out;

    void* degp = nullptr;
    cudaGetSymbolAddress(&degp, d_deg);
    cudaMemsetAsync(degp, 0, NN * sizeof(int));

    const int T = 256;
    const int ROWG = (NN * 32 + T - 1) / T;   // warp-per-row grids
    k_deg_tt     <<<DEG_BLKS + NODE_BLKS, T>>>(eh, Gu, Gi);
    k_scan2      <<<NB, 256>>>();
    k_scatter_ego<<<SCAT_BLKS + NODE_BLKS, T>>>(eh, et, Gu, Gi);
    k_row1attn   <<<ROWG, T>>>();
    k_row2       <<<ROWG, T>>>(Gu, Gi, out);
}

// round 13
// speedup vs baseline: 1.2275x; 1.0035x over previous
#include <cuda_runtime.h>
#include <cuda_fp16.h>

#define NUM_USERS 30000
#define NN 60000            // total nodes
#define EE 800000           // edges
#define KK 64               // embed dim (4 intents x 16)
#define NB 235              // ceil(NN/256) scan blocks

// -------- device scratch --------
__device__ __half d_TT16[(size_t)NN * KK];   // fp16 tanh(per-intent l2norm(ego))
__device__ __half d_EGO16[(size_t)NN * KK];  // fp16 ego[n]/sqrt(deg[n])
__device__ float  d_SC[(size_t)EE * 4];      // softmax scores at SORTED edge pos
__device__ int    d_deg[NN];
__device__ float  d_ratio[NN * 4];           // sqrt(deg[n]) * rsqrt(deg2[n,intent])
__device__ int    d_rowptr[NN + 1];
__device__ int    d_cursor[NN];
__device__ int    d_sorted_t[EE];            // tails grouped by head
__device__ int    d_partial[256];            // scan block sums
__device__ unsigned d_bar = 0;               // monotonic grid-barrier counter

__device__ __forceinline__ const float4* ego_row(const float* Gu, const float* Gi, int t) {
    const float* p = (t < NUM_USERS) ? (Gu + (size_t)t * KK)
                                     : (Gi + (size_t)(t - NUM_USERS) * KK);
    return reinterpret_cast<const float4*>(p);
}

__device__ __forceinline__ float4 h4_to_f4(uint2 p) {
    float2 a = __half22float2(*reinterpret_cast<const __half2*>(&p.x));
    float2 b = __half22float2(*reinterpret_cast<const __half2*>(&p.y));
    return make_float4(a.x, a.y, b.x, b.y);
}

__device__ __forceinline__ float fast_tanh(float x) {   // |x|<=1 here
    float e = __expf(2.f * x);
    return __fdividef(e - 1.f, e + 1.f);
}

// single-wave monotonic grid barrier (replay-safe; all blocks co-resident)
__device__ __forceinline__ void gridbar() {
    __syncthreads();
    if (threadIdx.x == 0) {
        __threadfence();
        atomicAdd(&d_bar, 1u);
        unsigned token;
        asm volatile("ld.acquire.gpu.global.u32 %0, [%1];" : "=r"(token) : "l"(&d_bar) : "memory");
        unsigned target = ((token - 1u) / gridDim.x + 1u) * gridDim.x;
        unsigned v = token;
        while (v < target) {
            __nanosleep(32);
            asm volatile("ld.acquire.gpu.global.u32 %0, [%1];" : "=r"(v) : "l"(&d_bar) : "memory");
        }
    }
    __syncthreads();
}

// block-wide exclusive scan of one int per thread (blockDim=256)
__device__ __forceinline__ int block_exscan(int v, int* sm) {
    int lane = threadIdx.x & 31, w = threadIdx.x >> 5;
    int x = v;
#pragma unroll
    for (int d = 1; d < 32; d <<= 1) {
        int y = __shfl_up_sync(0xffffffffu, x, d);
        if (lane >= d) x += y;
    }
    if (lane == 31) sm[w] = x;
    __syncthreads();
    if (w == 0) {
        int s = (lane < 8) ? sm[lane] : 0;
#pragma unroll
        for (int d = 1; d < 8; d <<= 1) {
            int y = __shfl_up_sync(0xffffffffu, s, d);
            if (lane >= d) s += y;
        }
        if (lane < 8) sm[lane] = s;
    }
    __syncthreads();
    int off = (w > 0) ? sm[w - 1] : 0;
    return off + x - v;
}

// -------- kernels --------

#define DEG_BLKS  ((EE / 8 + 255) / 256)
#define SCAT_BLKS ((EE / 8 + 255) / 256)
#define NODE_BLKS ((NN * 16 + 255) / 256)

// fused: blocks [0, DEG_BLKS) count head degrees (8 edges/thread); rest TT16
__global__ void k_deg_tt(const int* __restrict__ eh,
                         const float* __restrict__ Gu, const float* __restrict__ Gi) {
    if (blockIdx.x < DEG_BLKS) {
        int g = blockIdx.x * blockDim.x + threadIdx.x;
        if (g >= EE / 8) return;
        int4 a = __ldg(&reinterpret_cast<const int4*>(eh)[2 * g]);
        int4 b = __ldg(&reinterpret_cast<const int4*>(eh)[2 * g + 1]);
        atomicAdd(&d_deg[a.x], 1); atomicAdd(&d_deg[a.y], 1);
        atomicAdd(&d_deg[a.z], 1); atomicAdd(&d_deg[a.w], 1);
        atomicAdd(&d_deg[b.x], 1); atomicAdd(&d_deg[b.y], 1);
        atomicAdd(&d_deg[b.z], 1); atomicAdd(&d_deg[b.w], 1);
    } else {
        int tid = (blockIdx.x - DEG_BLKS) * blockDim.x + threadIdx.x;
        if (tid >= NN * 16) return;
        int n = tid >> 4;
        float4 v = __ldg(&ego_row(Gu, Gi, n)[tid & 15]);
        float ss = v.x * v.x + v.y * v.y + v.z * v.z + v.w * v.w;
        ss += __shfl_xor_sync(0xffffffffu, ss, 1);
        ss += __shfl_xor_sync(0xffffffffu, ss, 2);
        float it = rsqrtf(fmaxf(ss, 1e-12f));
        __half2 t0 = __floats2half2_rn(fast_tanh(v.x * it), fast_tanh(v.y * it));
        __half2 t1 = __floats2half2_rn(fast_tanh(v.z * it), fast_tanh(v.w * it));
        uint2 tp; tp.x = *reinterpret_cast<unsigned*>(&t0);
                  tp.y = *reinterpret_cast<unsigned*>(&t1);
        reinterpret_cast<uint2*>(d_TT16)[tid] = tp;
    }
}

// fused two-stage scan in one kernel (NB blocks = single wave; gridbar safe)
__global__ void k_scan2() {
    __shared__ int sm[8];
    __shared__ int base_sh;
    int i = blockIdx.x * 256 + threadIdx.x;
    int v = (i < NN) ? d_deg[i] : 0;
    int ex = block_exscan(v, sm);
    if (threadIdx.x == 255) d_partial[blockIdx.x] = ex + v;
    gridbar();
    if (threadIdx.x < 32) {
        int s = 0;
        for (int t = threadIdx.x; t < blockIdx.x; t += 32) s += d_partial[t];
#pragma unroll
        for (int d = 16; d >= 1; d >>= 1) s += __shfl_xor_sync(0xffffffffu, s, d);
        if (threadIdx.x == 0) base_sh = s;
    }
    __syncthreads();
    ex += base_sh;
    if (i < NN) { d_rowptr[i] = ex; d_cursor[i] = ex; }
    if (i == NN - 1) d_rowptr[NN] = EE;
}

// fused: blocks [0, SCAT_BLKS) scatter tails (8 edges/thread); rest EGO16
__global__ void k_scatter_ego(const int* __restrict__ eh, const int* __restrict__ et,
                              const float* __restrict__ Gu, const float* __restrict__ Gi) {
    if (blockIdx.x < SCAT_BLKS) {
        int g = blockIdx.x * blockDim.x + threadIdx.x;
        if (g >= EE / 8) return;
        int4 ha = __ldg(&reinterpret_cast<const int4*>(eh)[2 * g]);
        int4 hb = __ldg(&reinterpret_cast<const int4*>(eh)[2 * g + 1]);
        int4 ta = __ldg(&reinterpret_cast<const int4*>(et)[2 * g]);
        int4 tb = __ldg(&reinterpret_cast<const int4*>(et)[2 * g + 1]);
        d_sorted_t[atomicAdd(&d_cursor[ha.x], 1)] = ta.x;
        d_sorted_t[atomicAdd(&d_cursor[ha.y], 1)] = ta.y;
        d_sorted_t[atomicAdd(&d_cursor[ha.z], 1)] = ta.z;
        d_sorted_t[atomicAdd(&d_cursor[ha.w], 1)] = ta.w;
        d_sorted_t[atomicAdd(&d_cursor[hb.x], 1)] = tb.x;
        d_sorted_t[atomicAdd(&d_cursor[hb.y], 1)] = tb.y;
        d_sorted_t[atomicAdd(&d_cursor[hb.z], 1)] = tb.z;
        d_sorted_t[atomicAdd(&d_cursor[hb.w], 1)] = tb.w;
    } else {
        int tid = (blockIdx.x - SCAT_BLKS) * blockDim.x + threadIdx.x;
        if (tid >= NN * 16) return;
        int n = tid >> 4;
        float4 v = __ldg(&ego_row(Gu, Gi, n)[tid & 15]);
        float w = rsqrtf((float)d_deg[n]);   // rs1 folded into EGO16
        __half2 e0 = __floats2half2_rn(w * v.x, w * v.y);
        __half2 e1 = __floats2half2_rn(w * v.z, w * v.w);
        uint2 ep; ep.x = *reinterpret_cast<unsigned*>(&e0);
                  ep.y = *reinterpret_cast<unsigned*>(&e1);
        reinterpret_cast<uint2*>(d_EGO16)[tid] = ep;
    }
}

// Warp-per-row: SpMM1 (halves, fp16 load / fp32 accum) -> per-intent l2norm ->
// SMEM warp transpose -> half2 hv -> attention dot in HFMA2 -> ratio.
__global__ void __launch_bounds__(256, 6) k_row1attn() {
    __shared__ float hv_s[8][64];               // per-warp transpose buffer
    int wid = (blockIdx.x * blockDim.x + threadIdx.x) >> 5;
    if (wid >= NN) return;
    int lane = threadIdx.x & 31, half = lane >> 4, c = lane & 15;
    int wrp = (threadIdx.x >> 5);
    int start = d_rowptr[wid], end = d_rowptr[wid + 1];
    const uint2* EG = reinterpret_cast<const uint2*>(d_EGO16);

    // ---- pass 1: Z1 row accumulate (fp32) ----
    float4 acc = make_float4(0, 0, 0, 0);
    int j = start + half;
    for (; j + 2 < end; j += 4) {
        int t0 = __ldg(&d_sorted_t[j]);
        int t1 = __ldg(&d_sorted_t[j + 2]);
        float4 s0 = h4_to_f4(__ldg(&EG[(size_t)t0 * 16 + c]));
        float4 s1 = h4_to_f4(__ldg(&EG[(size_t)t1 * 16 + c]));
        acc.x += s0.x + s1.x; acc.y += s0.y + s1.y;
        acc.z += s0.z + s1.z; acc.w += s0.w + s1.w;
    }
    if (j < end) {
        int t = __ldg(&d_sorted_t[j]);
        float4 s = h4_to_f4(__ldg(&EG[(size_t)t * 16 + c]));
        acc.x += s.x; acc.y += s.y; acc.z += s.z; acc.w += s.w;
    }
    acc.x += __shfl_xor_sync(0xffffffffu, acc.x, 16);
    acc.y += __shfl_xor_sync(0xffffffffu, acc.y, 16);
    acc.z += __shfl_xor_sync(0xffffffffu, acc.z, 16);
    acc.w += __shfl_xor_sync(0xffffffffu, acc.w, 16);
    float ss = acc.x * acc.x + acc.y * acc.y + acc.z * acc.z + acc.w * acc.w;
    ss += __shfl_xor_sync(0xffffffffu, ss, 1);
    ss += __shfl_xor_sync(0xffffffffu, ss, 2);
    float ih = rsqrtf(fmaxf(ss, 1e-12f));

    // ---- SMEM warp transpose: half 0 stores chunk-layout hv; all lanes
    //      reload their intent's 16 channels (broadcast LDS, conflict-free) ----
    if (half == 0)
        *reinterpret_cast<float4*>(&hv_s[wrp][c * 4]) =
            make_float4(acc.x * ih, acc.y * ih, acc.z * ih, acc.w * ih);
    __syncwarp();
    int slot = lane >> 2, it = lane & 3;
    float4 hA = *reinterpret_cast<const float4*>(&hv_s[wrp][it * 16]);
    float4 hB = *reinterpret_cast<const float4*>(&hv_s[wrp][it * 16 + 4]);
    float4 hC = *reinterpret_cast<const float4*>(&hv_s[wrp][it * 16 + 8]);
    float4 hD = *reinterpret_cast<const float4*>(&hv_s[wrp][it * 16 + 12]);
    __half2 h2[8];
    h2[0] = __floats2half2_rn(hA.x, hA.y);
    h2[1] = __floats2half2_rn(hA.z, hA.w);
    h2[2] = __floats2half2_rn(hB.x, hB.y);
    h2[3] = __floats2half2_rn(hB.z, hB.w);
    h2[4] = __floats2half2_rn(hC.x, hC.y);
    h2[5] = __floats2half2_rn(hC.z, hC.w);
    h2[6] = __floats2half2_rn(hD.x, hD.y);
    h2[7] = __floats2half2_rn(hD.z, hD.w);

    // ---- pass 2: 8 edges/iter; lane=(slot,intent); native HFMA2 dot ----
    float dsum = 0.f;
    for (int base = start; base < end; base += 8) {
        int j2 = base + slot;
        bool act = (j2 < end);
        int t = act ? __ldg(&d_sorted_t[j2]) : 0;
        const uint4* bp = reinterpret_cast<const uint4*>(d_TT16 + ((size_t)t << 6)) + (it << 1);
        uint4 q0 = __ldg(bp);
        uint4 q1 = __ldg(bp + 1);
        // two independent HFMA2 chains for ILP
        __half2 pa = __hmul2(*reinterpret_cast<const __half2*>(&q0.x), h2[0]);
        __half2 pb = __hmul2(*reinterpret_cast<const __half2*>(&q0.y), h2[1]);
        pa = __hfma2(*reinterpret_cast<const __half2*>(&q0.z), h2[2], pa);
        pb = __hfma2(*reinterpret_cast<const __half2*>(&q0.w), h2[3], pb);
        pa = __hfma2(*reinterpret_cast<const __half2*>(&q1.x), h2[4], pa);
        pb = __hfma2(*reinterpret_cast<const __half2*>(&q1.y), h2[5], pb);
        pa = __hfma2(*reinterpret_cast<const __half2*>(&q1.z), h2[6], pa);
        pb = __hfma2(*reinterpret_cast<const __half2*>(&q1.w), h2[7], pb);
        float2 pf = __half22float2(__hadd2(pa, pb));
        float p = pf.x + pf.y;
        float ex = __expf(p);                       // "1+" & max-shift cancel
        float sum = ex + __shfl_xor_sync(0xffffffffu, ex, 1);
        sum += __shfl_xor_sync(0xffffffffu, sum, 2);
        float sc = __fdividef(ex, sum);
        if (act) {
            d_SC[(size_t)j2 * 4 + it] = sc;         // coalesced
            dsum += sc;
        }
    }
    dsum += __shfl_xor_sync(0xffffffffu, dsum, 4);
    dsum += __shfl_xor_sync(0xffffffffu, dsum, 8);
    dsum += __shfl_xor_sync(0xffffffffu, dsum, 16);
    if (lane < 4)
        d_ratio[wid * 4 + it] = sqrtf((float)(end - start)) * rsqrtf(dsum);
}

// warp-per-row SpMM2 (fp16 loads / fp32 accum) + final mean -> out.
//   w = SC[j]*ratio[t]; EGO16[t]=ego[t]/sqrt(deg[t])  ==  SC[j]*rsqrt(deg2[t])*ego[t]
__global__ void __launch_bounds__(256, 6)
k_row2(const float* __restrict__ Gu, const float* __restrict__ Gi,
       float* __restrict__ out) {
    int wid = (blockIdx.x * blockDim.x + threadIdx.x) >> 5;
    if (wid >= NN) return;
    int lane = threadIdx.x & 31, half = lane >> 4, c = lane & 15;
    int intent = c >> 2;
    int start = d_rowptr[wid], end = d_rowptr[wid + 1];
    const uint2* EG = reinterpret_cast<const uint2*>(d_EGO16);
    float4 acc = make_float4(0, 0, 0, 0);
    int j = start + half;
    for (; j + 2 < end; j += 4) {
        int t0 = __ldg(&d_sorted_t[j]);
        int t1 = __ldg(&d_sorted_t[j + 2]);
        float w0 = __ldg(&d_SC[(size_t)j * 4 + intent]) * __ldg(&d_ratio[t0 * 4 + intent]);
        float w1 = __ldg(&d_SC[(size_t)(j + 2) * 4 + intent]) * __ldg(&d_ratio[t1 * 4 + intent]);
        float4 s0 = h4_to_f4(__ldg(&EG[(size_t)t0 * 16 + c]));
        float4 s1 = h4_to_f4(__ldg(&EG[(size_t)t1 * 16 + c]));
        acc.x += w0 * s0.x + w1 * s1.x;
        acc.y += w0 * s0.y + w1 * s1.y;
        acc.z += w0 * s0.z + w1 * s1.z;
        acc.w += w0 * s0.w + w1 * s1.w;
    }
    if (j < end) {
        int t = __ldg(&d_sorted_t[j]);
        float w = __ldg(&d_SC[(size_t)j * 4 + intent]) * __ldg(&d_ratio[t * 4 + intent]);
        float4 s = h4_to_f4(__ldg(&EG[(size_t)t * 16 + c]));
        acc.x += w * s.x; acc.y += w * s.y; acc.z += w * s.z; acc.w += w * s.w;
    }
    acc.x += __shfl_xor_sync(0xffffffffu, acc.x, 16);
    acc.y += __shfl_xor_sync(0xffffffffu, acc.y, 16);
    acc.z += __shfl_xor_sync(0xffffffffu, acc.z, 16);
    acc.w += __shfl_xor_sync(0xffffffffu, acc.w, 16);
    if (half == 0) {
        float r2 = d_ratio[wid * 4 + intent] * rsqrtf((float)(end - start));
        float4 a = __ldg(&ego_row(Gu, Gi, wid)[c]);   // self term fp32
        reinterpret_cast<float4*>(out)[(size_t)wid * 16 + c] =
            make_float4(0.5f * (a.x + r2 * acc.x), 0.5f * (a.y + r2 * acc.y),
                        0.5f * (a.z + r2 * acc.z), 0.5f * (a.w + r2 * acc.w));
    }
}

extern "C" void kernel_launch(void* const* d_in, const int* in_sizes, int n_in,
                              void* d_out, int out_size) {
    const float* Gu = (const float*)d_in[0];
    const float* Gi = (const float*)d_in[1];
    const int*   eh = (const int*)d_in[2];
    const int*   et = (const int*)d_in[3];
    float* out = (float*)d_out;

    void* degp = nullptr;
    cudaGetSymbolAddress(&degp, d_deg);
    cudaMemsetAsync(degp, 0, NN * sizeof(int));

    const int T = 256;
    const int ROWG = (NN * 32 + T - 1) / T;   // warp-per-row grids
    k_deg_tt     <<<DEG_BLKS + NODE_BLKS, T>>>(eh, Gu, Gi);
    k_scan2      <<<NB, 256>>>();
    k_scatter_ego<<<SCAT_BLKS + NODE_BLKS, T>>>(eh, et, Gu, Gi);
    k_row1attn   <<<ROWG, T>>>();
    k_row2       <<<ROWG, T>>>(Gu, Gi, out);
}